// round 9
// baseline (speedup 1.0000x reference)
#include <cuda_runtime.h>
#include <cstdint>
#include <cstddef>

// AlarmworkRNN reduced form: only state row SEQ-1 (2047) reaches the output,
// so the scan collapses to a 256-step recurrence on two 1024-vectors.
//
// R9 = R8 (register-resident weights, proven) with the sync+exchange FUSED:
// each hidden column publishes one 16-byte packet {z1, z2, 0, tag} via a
// single 128-bit volatile store (NCCL LL128-style single-copy atomicity).
// Consumers poll the packets directly -- tag match implies the values in the
// same 16B word are valid. Deletes the producer fence, the flag atomicExch,
// the acquire fence, and the separate 12KB state-load phase from the chain.
// z12 is recomputed by consumers as z1+z2. Double-buffering + monotonic tags
// (replay-safe) unchanged from R5-R8.

#define ND   256
#define SEQ  2048
#define NI   256
#define NH   1024
#define NO   256
#define GRID 128
#define TPB  256
#define H_PER 8
#define O_PER 2
#define PAD  9          // staging transpose pad (conflict-free)
#define CPT  4          // columns polled per thread (1024/256)

// Publication k lives in buffer k&1. Packet: {z1_bits, z2_bits, 0, tag}.
__device__ uint4 g_pub[2][NH];    // zero-init; tags monotonic across replays

__device__ __forceinline__ uint4 ldv4(const uint4* p) {
    uint4 v;
    asm volatile("ld.volatile.global.v4.u32 {%0,%1,%2,%3}, [%4];"
                 : "=r"(v.x), "=r"(v.y), "=r"(v.z), "=r"(v.w)
                 : "l"(p) : "memory");
    return v;
}
__device__ __forceinline__ void stv4(uint4* p, uint4 v) {
    asm volatile("st.volatile.global.v4.u32 [%0], {%1,%2,%3,%4};"
                 :: "l"(p), "r"(v.x), "r"(v.y), "r"(v.z), "r"(v.w) : "memory");
}

__device__ __forceinline__ float warp_reduce(float a) {
    #pragma unroll
    for (int off = 16; off; off >>= 1)
        a += __shfl_xor_sync(0xffffffffu, a, off);
    return a;
}

extern __shared__ float smem[];
// floats: stg[9216] z12s[1024] z2s[1024] z1s[1024] xs[256]
#define OFF_STG  0
#define OFF_Z12  9216
#define OFF_Z2   10240
#define OFF_Z1   11264
#define OFF_XS   12288
#define SMEM_FLOATS 12544

__global__ void __launch_bounds__(TPB, 1)
rnn_kernel(const float* __restrict__ x,
           const float* __restrict__ W_in1, const float* __restrict__ b_in1,
           const float* __restrict__ W_rec1,
           const float* __restrict__ W_in2, const float* __restrict__ b_in2,
           const float* __restrict__ W_rec2,
           const float* __restrict__ W_out, const float* __restrict__ b_out,
           float* __restrict__ out) {
    float* stg  = smem + OFF_STG;
    float* z12s = smem + OFF_Z12;
    float* z2s  = smem + OFF_Z2;
    float* z1s  = smem + OFF_Z1;
    float* xs   = smem + OFF_XS;

    const int tid   = threadIdx.x;
    const int cta   = blockIdx.x;
    const int w     = tid >> 5;
    const int lane  = tid & 31;
    const int jbase = cta * H_PER;
    const int kbase = cta * O_PER;
    const int c0    = tid * CPT;          // this thread's polled columns

    // Launch-entry tag base: buffer 0 tags are uniform (base, = prev base+ND).
    const unsigned base = ldv4(&g_pub[0][c0]).w;

    // ---- Stage weights into REGISTERS via padded SMEM transpose (R8-verbatim) ----
    float wrec1[32], wrec2[32], win1[8], win2[8], wout[32];

    for (int r = tid >> 3; r < NH; r += 32)                 // W_rec1
        stg[r * PAD + (tid & 7)] = W_rec1[r * NH + jbase + (tid & 7)];
    __syncthreads();
    #pragma unroll
    for (int i = 0; i < 32; i++)
        wrec1[i] = stg[(lane + 32 * i) * PAD + w];
    __syncthreads();

    for (int r = tid >> 3; r < NH; r += 32)                 // W_rec2
        stg[r * PAD + (tid & 7)] = W_rec2[r * NH + jbase + (tid & 7)];
    __syncthreads();
    #pragma unroll
    for (int i = 0; i < 32; i++)
        wrec2[i] = stg[(lane + 32 * i) * PAD + w];
    __syncthreads();

    for (int r = tid >> 3; r < NI; r += 32)                 // W_in1
        stg[r * PAD + (tid & 7)] = W_in1[r * NH + jbase + (tid & 7)];
    __syncthreads();
    #pragma unroll
    for (int i = 0; i < 8; i++)
        win1[i] = stg[(lane + 32 * i) * PAD + w];
    __syncthreads();

    for (int r = tid >> 3; r < NI; r += 32)                 // W_in2
        stg[r * PAD + (tid & 7)] = W_in2[r * NH + jbase + (tid & 7)];
    __syncthreads();
    #pragma unroll
    for (int i = 0; i < 8; i++)
        win2[i] = stg[(lane + 32 * i) * PAD + w];
    __syncthreads();

    for (int r = tid >> 1; r < NH; r += 128)                // W_out (2 cols)
        stg[r * PAD + (tid & 1)] = W_out[r * NO + kbase + (tid & 1)];
    __syncthreads();
    if (w >= 6) {
        #pragma unroll
        for (int i = 0; i < 32; i++)
            wout[i] = stg[(lane + 32 * i) * PAD + (w - 6)];
    }

    const float b1 = b_in1[jbase + w];
    const float b2 = b_in2[jbase + w];
    const float bo = (w >= 6) ? b_out[kbase + (w - 6)] : 0.f;

    float z2reg = 0.f;   // warp-uniform: z2 value of column jbase+w

    // ---- Iteration 0: compute pub 1 from zero state, publish packet ----
    for (int i = tid; i < NH; i += TPB) { z12s[i] = 0.f; z2s[i] = 0.f; }
    xs[tid] = x[(size_t)(SEQ - 1) * NI + tid];          // x row 0
    __syncthreads();
    {
        float a1 = 0.f, a2 = 0.f;
        #pragma unroll
        for (int i = 0; i < 8; i++) {
            const float xv = xs[lane + 32 * i];
            a1 = fmaf(win1[i], xv, a1);
            a2 = fmaf(win2[i], xv, a2);
        }
        #pragma unroll
        for (int i = 0; i < 32; i++) {
            a1 = fmaf(wrec1[i], z12s[lane + 32 * i], a1);
            a2 = fmaf(wrec2[i], z2s [lane + 32 * i], a2);
        }
        a1 = warp_reduce(a1);
        a2 = warp_reduce(a2);
        const float z1n = tanhf(a1 + b1);
        z2reg = tanhf(a2 + b2);
        if (lane == 0) {          // publish pub 1 -> buffer 1, tag base+1
            uint4 pkt;
            pkt.x = __float_as_uint(z1n);
            pkt.y = __float_as_uint(z2reg);
            pkt.z = 0u;
            pkt.w = base + 1u;
            stv4(&g_pub[1][jbase + w], pkt);
        }
    }

    float xpref = __ldg(&x[((size_t)1 * SEQ + (SEQ - 1)) * NI + tid]);  // row 1

    // ---- Iterations 1..ND: poll pub t packets -> SMEM -> compute pub t+1 ----
    for (int t = 1; t <= ND; t++) {
        const int cb   = t & 1;
        const int nbuf = (t + 1) & 1;
        const bool ev  = ((t & 1) == 0);
        const unsigned target = base + (unsigned)t;

        // Poll own 4 packets: tag match => values in same 16B word are valid.
        uint4 v0, v1, v2, v3;
        do {
            v0 = ldv4(&g_pub[cb][c0 + 0]);
            v1 = ldv4(&g_pub[cb][c0 + 1]);
            v2 = ldv4(&g_pub[cb][c0 + 2]);
            v3 = ldv4(&g_pub[cb][c0 + 3]);
        } while (((int)(v0.w - target) < 0) | ((int)(v1.w - target) < 0) |
                 ((int)(v2.w - target) < 0) | ((int)(v3.w - target) < 0));

        __syncthreads();   // prior-iteration z1s readers (out matvec) done

        {
            const float a0 = __uint_as_float(v0.x), b0 = __uint_as_float(v0.y);
            const float a1_ = __uint_as_float(v1.x), b1_ = __uint_as_float(v1.y);
            const float a2_ = __uint_as_float(v2.x), b2_ = __uint_as_float(v2.y);
            const float a3_ = __uint_as_float(v3.x), b3_ = __uint_as_float(v3.y);
            z1s [c0 + 0] = a0;  z2s[c0 + 0] = b0;  z12s[c0 + 0] = a0 + b0;
            z1s [c0 + 1] = a1_; z2s[c0 + 1] = b1_; z12s[c0 + 1] = a1_ + b1_;
            z1s [c0 + 2] = a2_; z2s[c0 + 2] = b2_; z12s[c0 + 2] = a2_ + b2_;
            z1s [c0 + 3] = a3_; z2s[c0 + 3] = b3_; z12s[c0 + 3] = a3_ + b3_;
        }
        xs[tid] = xpref;
        __syncthreads();

        if (t < ND) {
            float a1 = 0.f, a2 = 0.f;
            #pragma unroll
            for (int i = 0; i < 8; i++) {
                const float xv = xs[lane + 32 * i];
                a1 = fmaf(win1[i], xv, a1);
                if (ev) a2 = fmaf(win2[i], xv, a2);
            }
            #pragma unroll
            for (int i = 0; i < 32; i++) {
                a1 = fmaf(wrec1[i], z12s[lane + 32 * i], a1);
                if (ev) a2 = fmaf(wrec2[i], z2s[lane + 32 * i], a2);
            }
            a1 = warp_reduce(a1);
            if (ev) a2 = warp_reduce(a2);

            const float z1n = tanhf(a1 + b1);
            if (ev) z2reg = tanhf(a2 + b2);
            if (lane == 0) {      // publish pub t+1 (single 128-bit packet)
                uint4 pkt;
                pkt.x = __float_as_uint(z1n);
                pkt.y = __float_as_uint(z2reg);   // odd t: republish held z2
                pkt.z = 0u;
                pkt.w = target + 1u;
                stv4(&g_pub[nbuf][jbase + w], pkt);
            }
        }

        // out[t-1] = tanh(z1(pub t) . Wout + bo) -- after publish, off path.
        if (w >= 6) {
            float a = 0.f;
            #pragma unroll
            for (int i = 0; i < 32; i++)
                a = fmaf(wout[i], z1s[lane + 32 * i], a);
            a = warp_reduce(a);
            if (lane == 0)
                out[(size_t)(t - 1) * NO + kbase + (w - 6)] = tanhf(a + bo);
        }

        // Prefetch x row t+1 (consumed next iteration; latency hidden).
        if (t + 1 < ND)
            xpref = __ldg(&x[((size_t)(t + 1) * SEQ + (SEQ - 1)) * NI + tid]);
    }
}

extern "C" void kernel_launch(void* const* d_in, const int* in_sizes, int n_in,
                              void* d_out, int out_size) {
    const float* x      = (const float*)d_in[0];
    const float* W_in1  = (const float*)d_in[1];
    const float* b_in1  = (const float*)d_in[2];
    const float* W_rec1 = (const float*)d_in[3];
    const float* W_in2  = (const float*)d_in[4];
    const float* b_in2  = (const float*)d_in[5];
    const float* W_rec2 = (const float*)d_in[6];
    const float* W_out  = (const float*)d_in[7];
    const float* b_out  = (const float*)d_in[8];
    float* out = (float*)d_out;

    const size_t shmem = SMEM_FLOATS * sizeof(float);
    cudaFuncSetAttribute(rnn_kernel, cudaFuncAttributeMaxDynamicSharedMemorySize,
                         (int)shmem);
    rnn_kernel<<<GRID, TPB, shmem>>>(x, W_in1, b_in1, W_rec1,
                                     W_in2, b_in2, W_rec2, W_out, b_out, out);
}